// round 1
// baseline (speedup 1.0000x reference)
#include <cuda_runtime.h>
#include <cuda_bf16.h>
#include <cstdint>

#define N_NODES 100000
#define N_EDGES 400000
#define N_GRAPHS 256
#define HID 256
#define LAYERS 3
#define EPSN 1e-5f

// ---------------- scratch (device globals; no allocations) ----------------
__device__ float g_h[N_NODES * HID];     // node features
__device__ float g_e[N_EDGES * HID];     // edge features (after edge MLP)
__device__ float g_z[N_NODES * HID];     // (1+eps)*h + agg
__device__ float g_t[N_NODES * HID];     // MLP intermediate
__device__ float g_gsum[N_GRAPHS * HID];
__device__ float g_gsq[N_GRAPHS * HID];
__device__ float g_cnt[N_GRAPHS];
__device__ float g_M4[4 * HID];          // edge_emb_W @ edge_mlp_W1
__device__ float g_c[HID];               // edge_emb_b @ W1 + b1
__device__ float g_cvec[HID];            // mean_bio @ head_W1[HID:] + head_b1

// ---------------- small helpers ----------------
__global__ void k_zero_cnt() {
    int i = threadIdx.x;
    if (i < N_GRAPHS) g_cnt[i] = 0.f;
}

__global__ void k_count(const int* __restrict__ batch) {
    int i = blockIdx.x * 256 + threadIdx.x;
    if (i < N_NODES) atomicAdd(&g_cnt[batch[i]], 1.0f);
}

__global__ void k_zero_stats() {
    int i = blockIdx.x * 256 + threadIdx.x;
    if (i < N_GRAPHS * HID) { g_gsum[i] = 0.f; g_gsq[i] = 0.f; }
}

// Precompute M4 = We@W1 (4x256), c = be@W1 + b1, cvec = bio@W1b + hb1
__global__ void k_prep(const float* __restrict__ We, const float* __restrict__ be,
                       const float* __restrict__ W1, const float* __restrict__ b1,
                       const float* __restrict__ bio, const float* __restrict__ hW1,
                       const float* __restrict__ hb1) {
    int k = threadIdx.x;  // 0..255
    if (blockIdx.x == 0) {
        float c = b1[k];
        #pragma unroll 4
        for (int i = 0; i < HID; i++) c += be[i] * W1[i * HID + k];
        g_c[k] = c;
        #pragma unroll
        for (int j = 0; j < 4; j++) {
            float m = 0.f;
            #pragma unroll 4
            for (int i = 0; i < HID; i++) m += We[j * HID + i] * W1[i * HID + k];
            g_M4[j * HID + k] = m;
        }
    } else {
        float cv = hb1[k];
        #pragma unroll 4
        for (int i = 0; i < 512; i++) cv += bio[i] * hW1[(HID + i) * HID + k];
        g_cvec[k] = cv;
    }
}

__global__ void k_embed(const int* __restrict__ x, const float* __restrict__ embW) {
    int idx = blockIdx.x * 256 + threadIdx.x;
    if (idx >= N_NODES * 64) return;
    int node = idx >> 6, ch = idx & 63;
    ((float4*)g_h)[node * 64 + ch] = ((const float4*)embW)[x[node] * 64 + ch];
}

__global__ void k_zinit(const float* __restrict__ epsp) {
    int idx = blockIdx.x * 256 + threadIdx.x;
    if (idx >= N_NODES * 64) return;
    float s = 1.0f + *epsp;
    float4 hv = ((const float4*)g_h)[idx];
    hv.x *= s; hv.y *= s; hv.z *= s; hv.w *= s;
    ((float4*)g_z)[idx] = hv;
}

// msg = relu(h[src] + e); scatter-add into z (pre-initialized with (1+eps)*h)
__global__ void k_msg(const int* __restrict__ src, const int* __restrict__ dst) {
    int idx = blockIdx.x * 256 + threadIdx.x;
    if (idx >= N_EDGES * 64) return;
    int e = idx >> 6, ch = idx & 63;
    int s = src[e], d = dst[e];
    float4 hv = ((const float4*)g_h)[s * 64 + ch];
    float4 ev = ((const float4*)g_e)[e * 64 + ch];
    float m0 = fmaxf(hv.x + ev.x, 0.f);
    float m1 = fmaxf(hv.y + ev.y, 0.f);
    float m2 = fmaxf(hv.z + ev.z, 0.f);
    float m3 = fmaxf(hv.w + ev.w, 0.f);
    float* zp = g_z + d * HID + ch * 4;
    atomicAdd(zp + 0, m0);
    atomicAdd(zp + 1, m1);
    atomicAdd(zp + 2, m2);
    atomicAdd(zp + 3, m3);
}

// ---------------- GEMM: C[M,256] = epilogue(A[M,256] @ B[256,256] + bias) ---------------
// MODE 0: A direct, no activation     (t @ W2 + b2 -> h)
// MODE 1: A direct, relu output       (z @ W1 + b1 -> t)
// MODE 2: A implicit = relu(edge_attr@M4 + c); output scaled by struct mask
// Inner loop uses packed fma.rn.f32x2 (bit-exact fp32, 2x FFMA rate on sm_103a).
template <int MODE>
__global__ void __launch_bounds__(256, 2) k_gemm(
    const float* __restrict__ A, const float* __restrict__ B,
    const float* __restrict__ bias, float* __restrict__ C, int M,
    const float* __restrict__ ssp) {
    __shared__ float As[8][128];
    __shared__ float Bs[8][128];
    __shared__ float4 ea_s[128];
    __shared__ float M4s[4][HID];
    __shared__ float cs[HID];

    const int tid = threadIdx.x;
    const int bm = blockIdx.x * 128;
    const int bn = blockIdx.y * 128;
    const int tx = tid & 15;   // 16 col-groups of 8
    const int ty = tid >> 4;   // 16 row-groups of 8

    if (MODE == 2) {
        if (tid < 128) {
            int r = bm + tid;
            ea_s[tid] = (r < M) ? ((const float4*)A)[r] : make_float4(0.f, 0.f, 0.f, 0.f);
        }
        ((float4*)M4s)[tid] = ((const float4*)g_M4)[tid];  // 1024 floats
        cs[tid] = g_c[tid];
        __syncthreads();
    }

    unsigned long long acc[8][4];
    #pragma unroll
    for (int i = 0; i < 8; i++)
        #pragma unroll
        for (int j = 0; j < 4; j++) acc[i][j] = 0ULL;

    const int arow = tid >> 1;
    const int acolh = (tid & 1) * 4;
    const int brow = tid >> 5;
    const int bcol = (tid & 31) * 4;

    for (int kc = 0; kc < HID; kc += 8) {
        if (MODE == 2) {
            float4 eav = ea_s[arow];
            #pragma unroll
            for (int kk = 0; kk < 4; kk++) {
                int k = acolh + kk;
                float v = cs[kc + k] + eav.x * M4s[0][kc + k] + eav.y * M4s[1][kc + k]
                        + eav.z * M4s[2][kc + k] + eav.w * M4s[3][kc + k];
                As[k][arow] = fmaxf(v, 0.f);
            }
        } else {
            int r = bm + arow;
            float4 av = (r < M) ? *(const float4*)(A + (size_t)r * HID + kc + acolh)
                                : make_float4(0.f, 0.f, 0.f, 0.f);
            As[acolh + 0][arow] = av.x;
            As[acolh + 1][arow] = av.y;
            As[acolh + 2][arow] = av.z;
            As[acolh + 3][arow] = av.w;
        }
        *(float4*)&Bs[brow][bcol] = *(const float4*)(B + (size_t)(kc + brow) * HID + bn + bcol);
        __syncthreads();

        #pragma unroll
        for (int k = 0; k < 8; k++) {
            float a[8];
            *(float4*)&a[0] = *(const float4*)&As[k][ty * 8];
            *(float4*)&a[4] = *(const float4*)&As[k][ty * 8 + 4];
            ulonglong2 bq0 = *(const ulonglong2*)&Bs[k][tx * 8];
            ulonglong2 bq1 = *(const ulonglong2*)&Bs[k][tx * 8 + 4];
            unsigned long long b2[4] = {bq0.x, bq0.y, bq1.x, bq1.y};
            #pragma unroll
            for (int i = 0; i < 8; i++) {
                unsigned ai = __float_as_uint(a[i]);
                unsigned long long a2;
                asm("mov.b64 %0, {%1, %1};" : "=l"(a2) : "r"(ai));
                #pragma unroll
                for (int j = 0; j < 4; j++)
                    asm("fma.rn.f32x2 %0, %1, %2, %0;" : "+l"(acc[i][j]) : "l"(a2), "l"(b2[j]));
            }
        }
        __syncthreads();
    }

    float sscale = 1.f;
    if (MODE == 2) sscale = *ssp;
    float bvals[8];
    *(float4*)&bvals[0] = *(const float4*)(bias + bn + tx * 8);
    *(float4*)&bvals[4] = *(const float4*)(bias + bn + tx * 8 + 4);

    #pragma unroll
    for (int i = 0; i < 8; i++) {
        int r = bm + ty * 8 + i;
        if (r < M) {
            float f = 1.f;
            if (MODE == 2) f = (ea_s[ty * 8 + i].y > 0.f) ? sscale : 1.f;
            float outv[8];
            #pragma unroll
            for (int j = 0; j < 4; j++) {
                float2 p = *(float2*)&acc[i][j];
                outv[2 * j] = p.x;
                outv[2 * j + 1] = p.y;
            }
            #pragma unroll
            for (int jj = 0; jj < 8; jj++) {
                float v = outv[jj] + bvals[jj];
                if (MODE == 1) v = fmaxf(v, 0.f);
                if (MODE == 2) v *= f;
                outv[jj] = v;
            }
            *(float4*)(C + (size_t)r * HID + bn + tx * 8) = *(float4*)&outv[0];
            *(float4*)(C + (size_t)r * HID + bn + tx * 8 + 4) = *(float4*)&outv[4];
        }
    }
}

// ---------------- segmented (per-graph) reductions: batch is sorted ----------------
#define STRIP 64

__global__ void k_gsum(const float* __restrict__ h, const int* __restrict__ batch) {
    __shared__ int bs[STRIP];
    int c = threadIdx.x;
    int n0 = blockIdx.x * STRIP;
    int n1 = min(n0 + STRIP, N_NODES);
    if (c < STRIP && n0 + c < N_NODES) bs[c] = batch[n0 + c];
    __syncthreads();
    float acc = 0.f;
    int cur = bs[0];
    for (int n = n0; n < n1; n++) {
        int b = bs[n - n0];
        if (b != cur) {
            atomicAdd(&g_gsum[cur * HID + c], acc);
            acc = 0.f;
            cur = b;
        }
        acc += h[(size_t)n * HID + c];
    }
    atomicAdd(&g_gsum[cur * HID + c], acc);
}

__global__ void k_gsq(const float* __restrict__ h, const int* __restrict__ batch,
                      const float* __restrict__ alpha) {
    __shared__ int bs[STRIP];
    int c = threadIdx.x;
    int n0 = blockIdx.x * STRIP;
    int n1 = min(n0 + STRIP, N_NODES);
    if (c < STRIP && n0 + c < N_NODES) bs[c] = batch[n0 + c];
    __syncthreads();
    float alpha_c = alpha[c];
    int cur = bs[0];
    float inv = 1.f / fmaxf(g_cnt[cur], 1.f);
    float meanv = g_gsum[cur * HID + c] * inv;
    float acc = 0.f;
    for (int n = n0; n < n1; n++) {
        int b = bs[n - n0];
        if (b != cur) {
            atomicAdd(&g_gsq[cur * HID + c], acc);
            acc = 0.f;
            cur = b;
            inv = 1.f / fmaxf(g_cnt[cur], 1.f);
            meanv = g_gsum[cur * HID + c] * inv;
        }
        float hc = h[(size_t)n * HID + c] - alpha_c * meanv;
        acc += hc * hc;
    }
    atomicAdd(&g_gsq[cur * HID + c], acc);
}

__global__ void k_norm(const int* __restrict__ batch, const float* __restrict__ gamma,
                       const float* __restrict__ beta, const float* __restrict__ alpha) {
    int idx = blockIdx.x * 256 + threadIdx.x;
    if (idx >= N_NODES * HID) return;
    int node = idx >> 8, c = idx & 255;
    int b = batch[node];
    float inv = 1.f / fmaxf(g_cnt[b], 1.f);
    float mean = g_gsum[b * HID + c] * inv;
    float var = g_gsq[b * HID + c] * inv;
    float hc = g_h[idx] - alpha[c] * mean;
    g_h[idx] = gamma[c] * hc * rsqrtf(var + EPSN) + beta[c];
}

// ---------------- head: per-graph MLP (bio part folded into g_cvec) ----------------
__global__ void k_head(const float* __restrict__ headW1, const float* __restrict__ headW2,
                       const float* __restrict__ headb2, float* __restrict__ out) {
    int g = blockIdx.x;
    int j = threadIdx.x;
    __shared__ float gs[HID];
    __shared__ float red[HID];
    float inv = 1.f / fmaxf(g_cnt[g], 1.f);
    gs[j] = g_gsum[g * HID + j] * inv;
    __syncthreads();
    float acc = g_cvec[j];
    #pragma unroll 8
    for (int k = 0; k < HID; k++) acc += gs[k] * headW1[k * HID + j];
    acc = fmaxf(acc, 0.f);
    red[j] = acc * headW2[j];
    __syncthreads();
    for (int s = 128; s > 0; s >>= 1) {
        if (j < s) red[j] += red[j + s];
        __syncthreads();
    }
    if (j == 0) out[g] = red[0] + headb2[0];
}

// ---------------- launcher ----------------
extern "C" void kernel_launch(void* const* d_in, const int* in_sizes, int n_in,
                              void* d_out, int out_size) {
    const int* x = (const int*)d_in[0];
    const int* edge_index = (const int*)d_in[1];
    const float* edge_attr = (const float*)d_in[2];
    const int* batch = (const int*)d_in[3];
    const float* node_emb_W = (const float*)d_in[4];
    const float* edge_emb_W = (const float*)d_in[5];
    const float* edge_emb_b = (const float*)d_in[6];
    const float* edge_mlp_W1 = (const float*)d_in[7];
    const float* edge_mlp_b1 = (const float*)d_in[8];
    const float* edge_mlp_W2 = (const float*)d_in[9];
    const float* edge_mlp_b2 = (const float*)d_in[10];
    const float* struct_scale = (const float*)d_in[11];
    const float* conv_W1 = (const float*)d_in[12];
    const float* conv_b1 = (const float*)d_in[13];
    const float* conv_W2 = (const float*)d_in[14];
    const float* conv_b2 = (const float*)d_in[15];
    const float* conv_eps = (const float*)d_in[16];
    const float* norm_gamma = (const float*)d_in[17];
    const float* norm_beta = (const float*)d_in[18];
    const float* norm_alpha = (const float*)d_in[19];
    // mean_bio = d_in[20], head_W1 = d_in[21], head_b1 = d_in[22]
    const float* head_W1 = (const float*)d_in[21];
    const float* head_W2 = (const float*)d_in[23];
    const float* head_b2 = (const float*)d_in[24];
    float* out = (float*)d_out;

    const int* src = edge_index;
    const int* dst = edge_index + N_EDGES;

    // prep: counts, folded constants, embedding
    k_zero_cnt<<<1, 256>>>();
    k_count<<<(N_NODES + 255) / 256, 256>>>(batch);
    k_prep<<<2, 256>>>(edge_emb_W, edge_emb_b, edge_mlp_W1, edge_mlp_b1,
                       (const float*)d_in[20], head_W1, (const float*)d_in[22]);
    k_embed<<<(N_NODES * 64 + 255) / 256, 256>>>(x, node_emb_W);

    // edge MLP fused GEMM: e = (relu(edge_attr@M4 + c)) @ W2 + b2, struct-scaled
    k_gemm<2><<<dim3(N_EDGES / 128, 2), 256>>>(edge_attr, edge_mlp_W2, edge_mlp_b2,
                                               g_e, N_EDGES, struct_scale);

    const int gemm_mx = (N_NODES + 127) / 128;
    for (int l = 0; l < LAYERS; l++) {
        k_zinit<<<(N_NODES * 64 + 255) / 256, 256>>>(conv_eps + l);
        k_msg<<<(N_EDGES * 64 + 255) / 256, 256>>>(src, dst);
        k_gemm<1><<<dim3(gemm_mx, 2), 256>>>(g_z, conv_W1 + (size_t)l * HID * HID,
                                             conv_b1 + l * HID, g_t, N_NODES, nullptr);
        k_gemm<0><<<dim3(gemm_mx, 2), 256>>>(g_t, conv_W2 + (size_t)l * HID * HID,
                                             conv_b2 + l * HID, g_h, N_NODES, nullptr);
        k_zero_stats<<<(N_GRAPHS * HID + 255) / 256, 256>>>();
        k_gsum<<<(N_NODES + STRIP - 1) / STRIP, 256>>>(g_h, batch);
        k_gsq<<<(N_NODES + STRIP - 1) / STRIP, 256>>>(g_h, batch, norm_alpha + l * HID);
        k_norm<<<(N_NODES * HID + 255) / 256, 256>>>(batch, norm_gamma + l * HID,
                                                     norm_beta + l * HID, norm_alpha + l * HID);
    }

    // pool + head
    k_zero_stats<<<(N_GRAPHS * HID + 255) / 256, 256>>>();
    k_gsum<<<(N_NODES + STRIP - 1) / STRIP, 256>>>(g_h, batch);
    k_head<<<N_GRAPHS, 256>>>(head_W1, head_W2, head_b2, out);
}

// round 2
// speedup vs baseline: 1.0477x; 1.0477x over previous
#include <cuda_runtime.h>
#include <cuda_bf16.h>
#include <cstdint>

#define N_NODES 100000
#define N_EDGES 400000
#define N_GRAPHS 256
#define HID 256
#define LAYERS 3
#define EPSN 1e-5f
#define KSTEP 16
#define NTILES (HID / KSTEP)

// ---------------- scratch (device globals; no allocations) ----------------
__device__ float g_h[N_NODES * HID];     // node features
__device__ float g_e[N_EDGES * HID];     // edge features (after edge MLP)
__device__ float g_z[N_NODES * HID];     // (1+eps)*h + agg
__device__ float g_t[N_NODES * HID];     // MLP intermediate
__device__ float g_gsum[N_GRAPHS * HID];
__device__ float g_gsq[N_GRAPHS * HID];
__device__ float g_cnt[N_GRAPHS];
__device__ float g_M4[4 * HID];          // edge_emb_W @ edge_mlp_W1
__device__ float g_c[HID];               // edge_emb_b @ W1 + b1
__device__ float g_cvec[HID];            // mean_bio @ head_W1[HID:] + head_b1

// ---------------- small helpers ----------------
__global__ void k_zero_cnt() {
    int i = threadIdx.x;
    if (i < N_GRAPHS) g_cnt[i] = 0.f;
}

__global__ void k_count(const int* __restrict__ batch) {
    int i = blockIdx.x * 256 + threadIdx.x;
    if (i < N_NODES) atomicAdd(&g_cnt[batch[i]], 1.0f);
}

__global__ void k_zero_stats() {
    int i = blockIdx.x * 256 + threadIdx.x;
    if (i < N_GRAPHS * HID) { g_gsum[i] = 0.f; g_gsq[i] = 0.f; }
}

// Precompute M4 = We@W1 (4x256), c = be@W1 + b1, cvec = bio@W1b + hb1
__global__ void k_prep(const float* __restrict__ We, const float* __restrict__ be,
                       const float* __restrict__ W1, const float* __restrict__ b1,
                       const float* __restrict__ bio, const float* __restrict__ hW1,
                       const float* __restrict__ hb1) {
    int k = threadIdx.x;  // 0..255
    if (blockIdx.x == 0) {
        float c = b1[k];
        #pragma unroll 4
        for (int i = 0; i < HID; i++) c += be[i] * W1[i * HID + k];
        g_c[k] = c;
        #pragma unroll
        for (int j = 0; j < 4; j++) {
            float m = 0.f;
            #pragma unroll 4
            for (int i = 0; i < HID; i++) m += We[j * HID + i] * W1[i * HID + k];
            g_M4[j * HID + k] = m;
        }
    } else {
        float cv = hb1[k];
        #pragma unroll 4
        for (int i = 0; i < 512; i++) cv += bio[i] * hW1[(HID + i) * HID + k];
        g_cvec[k] = cv;
    }
}

__global__ void k_embed(const int* __restrict__ x, const float* __restrict__ embW) {
    int idx = blockIdx.x * 256 + threadIdx.x;
    if (idx >= N_NODES * 64) return;
    int node = idx >> 6, ch = idx & 63;
    ((float4*)g_h)[node * 64 + ch] = ((const float4*)embW)[x[node] * 64 + ch];
}

__global__ void k_zinit(const float* __restrict__ epsp) {
    int idx = blockIdx.x * 256 + threadIdx.x;
    if (idx >= N_NODES * 64) return;
    float s = 1.0f + *epsp;
    float4 hv = ((const float4*)g_h)[idx];
    hv.x *= s; hv.y *= s; hv.z *= s; hv.w *= s;
    ((float4*)g_z)[idx] = hv;
}

// msg = relu(h[src] + e); scatter-add into z (pre-initialized with (1+eps)*h)
__global__ void k_msg(const int* __restrict__ src, const int* __restrict__ dst) {
    int idx = blockIdx.x * 256 + threadIdx.x;
    if (idx >= N_EDGES * 64) return;
    int e = idx >> 6, ch = idx & 63;
    int s = src[e], d = dst[e];
    float4 hv = ((const float4*)g_h)[s * 64 + ch];
    float4 ev = ((const float4*)g_e)[e * 64 + ch];
    float m0 = fmaxf(hv.x + ev.x, 0.f);
    float m1 = fmaxf(hv.y + ev.y, 0.f);
    float m2 = fmaxf(hv.z + ev.z, 0.f);
    float m3 = fmaxf(hv.w + ev.w, 0.f);
    float* zp = g_z + d * HID + ch * 4;
    atomicAdd(zp + 0, m0);
    atomicAdd(zp + 1, m1);
    atomicAdd(zp + 2, m2);
    atomicAdd(zp + 3, m3);
}

// ---------------- GEMM: C[M,256] = epilogue(A[M,256] @ B[256,256] + bias) ---------------
// MODE 0: A direct, no activation     (t @ W2 + b2 -> h)
// MODE 1: A direct, relu output       (z @ W1 + b1 -> t)
// MODE 2: A implicit = relu(edge_attr@M4 + c); output scaled by struct mask
// 128x128 tile, 256 threads, 8x8 per-thread micro-tile, K-step 16, double-buffered.
// Inner loop: packed fma.rn.f32x2 (bit-exact fp32, 2x FFMA issue rate on sm_103a).
template <int MODE>
__global__ void __launch_bounds__(256) k_gemm(
    const float* __restrict__ A, const float* __restrict__ B,
    const float* __restrict__ bias, float* __restrict__ C, int M,
    const float* __restrict__ ssp) {
    __shared__ float As[2][KSTEP][128];
    __shared__ float Bs[2][KSTEP][128];
    __shared__ float4 ea_s[128];
    __shared__ float M4s[4][HID];
    __shared__ float cs[HID];

    const int tid = threadIdx.x;
    const int bm = blockIdx.x * 128;
    const int bn = blockIdx.y * 128;
    const int tx = tid & 15;   // 16 col-groups of 8
    const int ty = tid >> 4;   // 16 row-groups of 8

    // MODE2: per-thread fixed edge row for A-fill
    const int fm = tid & 127;          // m index this thread fills
    const int fk0 = tid >> 7;          // base k offset (0 or 1)
    float4 eav = make_float4(0.f, 0.f, 0.f, 0.f);

    if (MODE == 2) {
        if (tid < 128) {
            int r = bm + tid;
            ea_s[tid] = (r < M) ? ((const float4*)A)[r] : make_float4(0.f, 0.f, 0.f, 0.f);
        }
        ((float4*)M4s)[tid] = ((const float4*)g_M4)[tid];  // 1024 floats
        cs[tid] = g_c[tid];
        __syncthreads();
        eav = ea_s[fm];
    }

    // staging registers for global->smem double buffer
    float4 ra[2], rb[2];
    const int a_m = tid & 127;        // A load: row within tile
    const int a_kg = tid >> 7;        // A load: k-group base (0/1), +2 for second
    const int b_k = tid >> 5;         // B load: k row (0..7), +8 for second
    const int b_n4 = tid & 31;        // B load: float4 col

    // ---- prologue: fill buffer 0 ----
    if (MODE == 2) {
        #pragma unroll
        for (int l = 0; l < 8; l++) {
            int k = fk0 + l * 2;
            float v = cs[k] + eav.x * M4s[0][k] + eav.y * M4s[1][k]
                    + eav.z * M4s[2][k] + eav.w * M4s[3][k];
            As[0][k][fm] = fmaxf(v, 0.f);
        }
    } else {
        #pragma unroll
        for (int l = 0; l < 2; l++) {
            int kg = a_kg + l * 2;
            int r = bm + a_m;
            ra[l] = (r < M) ? *(const float4*)(A + (size_t)r * HID + kg * 4)
                            : make_float4(0.f, 0.f, 0.f, 0.f);
            As[0][kg * 4 + 0][a_m] = ra[l].x;
            As[0][kg * 4 + 1][a_m] = ra[l].y;
            As[0][kg * 4 + 2][a_m] = ra[l].z;
            As[0][kg * 4 + 3][a_m] = ra[l].w;
        }
    }
    #pragma unroll
    for (int l = 0; l < 2; l++) {
        int k = b_k + l * 8;
        rb[l] = *(const float4*)(B + (size_t)k * HID + bn + b_n4 * 4);
        *(float4*)&Bs[0][k][b_n4 * 4] = rb[l];
    }
    __syncthreads();

    unsigned long long acc[8][4];
    #pragma unroll
    for (int i = 0; i < 8; i++)
        #pragma unroll
        for (int j = 0; j < 4; j++) acc[i][j] = 0ULL;

    for (int t = 0; t < NTILES; t++) {
        const int cur = t & 1, nxt = cur ^ 1;
        const int kc_next = (t + 1) * KSTEP;

        // stage next tile's global loads early (latency overlaps compute)
        if (t + 1 < NTILES) {
            if (MODE != 2) {
                #pragma unroll
                for (int l = 0; l < 2; l++) {
                    int kg = a_kg + l * 2;
                    int r = bm + a_m;
                    ra[l] = (r < M) ? *(const float4*)(A + (size_t)r * HID + kc_next + kg * 4)
                                    : make_float4(0.f, 0.f, 0.f, 0.f);
                }
            }
            #pragma unroll
            for (int l = 0; l < 2; l++) {
                int k = b_k + l * 8;
                rb[l] = *(const float4*)(B + (size_t)(kc_next + k) * HID + bn + b_n4 * 4);
            }
        }

        // compute on current buffer
        #pragma unroll
        for (int k = 0; k < KSTEP; k++) {
            float a[8];
            *(float4*)&a[0] = *(const float4*)&As[cur][k][ty * 8];
            *(float4*)&a[4] = *(const float4*)&As[cur][k][ty * 8 + 4];
            ulonglong2 bq0 = *(const ulonglong2*)&Bs[cur][k][tx * 8];
            ulonglong2 bq1 = *(const ulonglong2*)&Bs[cur][k][tx * 8 + 4];
            unsigned long long b2[4] = {bq0.x, bq0.y, bq1.x, bq1.y};
            #pragma unroll
            for (int i = 0; i < 8; i++) {
                unsigned ai = __float_as_uint(a[i]);
                unsigned long long a2;
                asm("mov.b64 %0, {%1, %1};" : "=l"(a2) : "r"(ai));
                #pragma unroll
                for (int j = 0; j < 4; j++)
                    asm("fma.rn.f32x2 %0, %1, %2, %0;" : "+l"(acc[i][j]) : "l"(a2), "l"(b2[j]));
            }
        }

        // write staged data into next buffer
        if (t + 1 < NTILES) {
            if (MODE == 2) {
                #pragma unroll
                for (int l = 0; l < 8; l++) {
                    int k = fk0 + l * 2;
                    int kk = kc_next + k;
                    float v = cs[kk] + eav.x * M4s[0][kk] + eav.y * M4s[1][kk]
                            + eav.z * M4s[2][kk] + eav.w * M4s[3][kk];
                    As[nxt][k][fm] = fmaxf(v, 0.f);
                }
            } else {
                #pragma unroll
                for (int l = 0; l < 2; l++) {
                    int kg = a_kg + l * 2;
                    As[nxt][kg * 4 + 0][a_m] = ra[l].x;
                    As[nxt][kg * 4 + 1][a_m] = ra[l].y;
                    As[nxt][kg * 4 + 2][a_m] = ra[l].z;
                    As[nxt][kg * 4 + 3][a_m] = ra[l].w;
                }
            }
            #pragma unroll
            for (int l = 0; l < 2; l++) {
                int k = b_k + l * 8;
                *(float4*)&Bs[nxt][k][b_n4 * 4] = rb[l];
            }
        }
        __syncthreads();
    }

    float sscale = 1.f;
    if (MODE == 2) sscale = *ssp;
    float bvals[8];
    *(float4*)&bvals[0] = *(const float4*)(bias + bn + tx * 8);
    *(float4*)&bvals[4] = *(const float4*)(bias + bn + tx * 8 + 4);

    #pragma unroll
    for (int i = 0; i < 8; i++) {
        int r = bm + ty * 8 + i;
        if (r < M) {
            float f = 1.f;
            if (MODE == 2) f = (ea_s[ty * 8 + i].y > 0.f) ? sscale : 1.f;
            float outv[8];
            #pragma unroll
            for (int j = 0; j < 4; j++) {
                float2 p = *(float2*)&acc[i][j];
                outv[2 * j] = p.x;
                outv[2 * j + 1] = p.y;
            }
            #pragma unroll
            for (int jj = 0; jj < 8; jj++) {
                float v = outv[jj] + bvals[jj];
                if (MODE == 1) v = fmaxf(v, 0.f);
                if (MODE == 2) v *= f;
                outv[jj] = v;
            }
            *(float4*)(C + (size_t)r * HID + bn + tx * 8) = *(float4*)&outv[0];
            *(float4*)(C + (size_t)r * HID + bn + tx * 8 + 4) = *(float4*)&outv[4];
        }
    }
}

// ---------------- segmented (per-graph) reductions: batch is sorted ----------------
#define STRIP 64

__global__ void k_gsum(const float* __restrict__ h, const int* __restrict__ batch) {
    __shared__ int bs[STRIP];
    int c = threadIdx.x;
    int n0 = blockIdx.x * STRIP;
    int n1 = min(n0 + STRIP, N_NODES);
    if (c < STRIP && n0 + c < N_NODES) bs[c] = batch[n0 + c];
    __syncthreads();
    float acc = 0.f;
    int cur = bs[0];
    for (int n = n0; n < n1; n++) {
        int b = bs[n - n0];
        if (b != cur) {
            atomicAdd(&g_gsum[cur * HID + c], acc);
            acc = 0.f;
            cur = b;
        }
        acc += h[(size_t)n * HID + c];
    }
    atomicAdd(&g_gsum[cur * HID + c], acc);
}

__global__ void k_gsq(const float* __restrict__ h, const int* __restrict__ batch,
                      const float* __restrict__ alpha) {
    __shared__ int bs[STRIP];
    int c = threadIdx.x;
    int n0 = blockIdx.x * STRIP;
    int n1 = min(n0 + STRIP, N_NODES);
    if (c < STRIP && n0 + c < N_NODES) bs[c] = batch[n0 + c];
    __syncthreads();
    float alpha_c = alpha[c];
    int cur = bs[0];
    float inv = 1.f / fmaxf(g_cnt[cur], 1.f);
    float meanv = g_gsum[cur * HID + c] * inv;
    float acc = 0.f;
    for (int n = n0; n < n1; n++) {
        int b = bs[n - n0];
        if (b != cur) {
            atomicAdd(&g_gsq[cur * HID + c], acc);
            acc = 0.f;
            cur = b;
            inv = 1.f / fmaxf(g_cnt[cur], 1.f);
            meanv = g_gsum[cur * HID + c] * inv;
        }
        float hc = h[(size_t)n * HID + c] - alpha_c * meanv;
        acc += hc * hc;
    }
    atomicAdd(&g_gsq[cur * HID + c], acc);
}

__global__ void k_norm(const int* __restrict__ batch, const float* __restrict__ gamma,
                       const float* __restrict__ beta, const float* __restrict__ alpha) {
    int idx = blockIdx.x * 256 + threadIdx.x;
    if (idx >= N_NODES * HID) return;
    int node = idx >> 8, c = idx & 255;
    int b = batch[node];
    float inv = 1.f / fmaxf(g_cnt[b], 1.f);
    float mean = g_gsum[b * HID + c] * inv;
    float var = g_gsq[b * HID + c] * inv;
    float hc = g_h[idx] - alpha[c] * mean;
    g_h[idx] = gamma[c] * hc * rsqrtf(var + EPSN) + beta[c];
}

// ---------------- head: per-graph MLP (bio part folded into g_cvec) ----------------
__global__ void k_head(const float* __restrict__ headW1, const float* __restrict__ headW2,
                       const float* __restrict__ headb2, float* __restrict__ out) {
    int g = blockIdx.x;
    int j = threadIdx.x;
    __shared__ float gs[HID];
    __shared__ float red[HID];
    float inv = 1.f / fmaxf(g_cnt[g], 1.f);
    gs[j] = g_gsum[g * HID + j] * inv;
    __syncthreads();
    float acc = g_cvec[j];
    #pragma unroll 8
    for (int k = 0; k < HID; k++) acc += gs[k] * headW1[k * HID + j];
    acc = fmaxf(acc, 0.f);
    red[j] = acc * headW2[j];
    __syncthreads();
    for (int s = 128; s > 0; s >>= 1) {
        if (j < s) red[j] += red[j + s];
        __syncthreads();
    }
    if (j == 0) out[g] = red[0] + headb2[0];
}

// ---------------- launcher ----------------
extern "C" void kernel_launch(void* const* d_in, const int* in_sizes, int n_in,
                              void* d_out, int out_size) {
    const int* x = (const int*)d_in[0];
    const int* edge_index = (const int*)d_in[1];
    const float* edge_attr = (const float*)d_in[2];
    const int* batch = (const int*)d_in[3];
    const float* node_emb_W = (const float*)d_in[4];
    const float* edge_emb_W = (const float*)d_in[5];
    const float* edge_emb_b = (const float*)d_in[6];
    const float* edge_mlp_W1 = (const float*)d_in[7];
    const float* edge_mlp_b1 = (const float*)d_in[8];
    const float* edge_mlp_W2 = (const float*)d_in[9];
    const float* edge_mlp_b2 = (const float*)d_in[10];
    const float* struct_scale = (const float*)d_in[11];
    const float* conv_W1 = (const float*)d_in[12];
    const float* conv_b1 = (const float*)d_in[13];
    const float* conv_W2 = (const float*)d_in[14];
    const float* conv_b2 = (const float*)d_in[15];
    const float* conv_eps = (const float*)d_in[16];
    const float* norm_gamma = (const float*)d_in[17];
    const float* norm_beta = (const float*)d_in[18];
    const float* norm_alpha = (const float*)d_in[19];
    const float* head_W1 = (const float*)d_in[21];
    const float* head_W2 = (const float*)d_in[23];
    const float* head_b2 = (const float*)d_in[24];
    float* out = (float*)d_out;

    const int* src = edge_index;
    const int* dst = edge_index + N_EDGES;

    // prep: counts, folded constants, embedding
    k_zero_cnt<<<1, 256>>>();
    k_count<<<(N_NODES + 255) / 256, 256>>>(batch);
    k_prep<<<2, 256>>>(edge_emb_W, edge_emb_b, edge_mlp_W1, edge_mlp_b1,
                       (const float*)d_in[20], head_W1, (const float*)d_in[22]);
    k_embed<<<(N_NODES * 64 + 255) / 256, 256>>>(x, node_emb_W);

    // edge MLP fused GEMM: e = (relu(edge_attr@M4 + c)) @ W2 + b2, struct-scaled
    k_gemm<2><<<dim3(N_EDGES / 128, 2), 256>>>(edge_attr, edge_mlp_W2, edge_mlp_b2,
                                               g_e, N_EDGES, struct_scale);

    const int gemm_mx = (N_NODES + 127) / 128;
    for (int l = 0; l < LAYERS; l++) {
        k_zinit<<<(N_NODES * 64 + 255) / 256, 256>>>(conv_eps + l);
        k_msg<<<(N_EDGES * 64 + 255) / 256, 256>>>(src, dst);
        k_gemm<1><<<dim3(gemm_mx, 2), 256>>>(g_z, conv_W1 + (size_t)l * HID * HID,
                                             conv_b1 + l * HID, g_t, N_NODES, nullptr);
        k_gemm<0><<<dim3(gemm_mx, 2), 256>>>(g_t, conv_W2 + (size_t)l * HID * HID,
                                             conv_b2 + l * HID, g_h, N_NODES, nullptr);
        k_zero_stats<<<(N_GRAPHS * HID + 255) / 256, 256>>>();
        k_gsum<<<(N_NODES + STRIP - 1) / STRIP, 256>>>(g_h, batch);
        k_gsq<<<(N_NODES + STRIP - 1) / STRIP, 256>>>(g_h, batch, norm_alpha + l * HID);
        k_norm<<<(N_NODES * HID + 255) / 256, 256>>>(batch, norm_gamma + l * HID,
                                                     norm_beta + l * HID, norm_alpha + l * HID);
    }

    // pool + head
    k_zero_stats<<<(N_GRAPHS * HID + 255) / 256, 256>>>();
    k_gsum<<<(N_NODES + STRIP - 1) / STRIP, 256>>>(g_h, batch);
    k_head<<<N_GRAPHS, 256>>>(head_W1, head_W2, head_b2, out);
}

// round 4
// speedup vs baseline: 1.2542x; 1.1971x over previous
#include <cuda_runtime.h>
#include <cuda_bf16.h>
#include <cstdint>

#define N_NODES 100000
#define N_EDGES 400000
#define N_GRAPHS 256
#define HID 256
#define LAYERS 3
#define EPSN 1e-5f
#define KSTEP 16
#define NTILES (HID / KSTEP)

// ---------------- scratch (device globals; no allocations) ----------------
__device__ float g_h[N_NODES * HID];     // node features
__device__ float g_e[N_EDGES * HID];     // edge features (after edge MLP)
__device__ float g_z[N_NODES * HID];     // (1+eps)*h + agg
__device__ float g_t[N_NODES * HID];     // MLP intermediate
__device__ float g_gsum[N_GRAPHS * HID];
__device__ float g_gsq[N_GRAPHS * HID];
__device__ float g_cnt[N_GRAPHS];
__device__ float g_M4[4 * HID];          // edge_emb_W @ edge_mlp_W1
__device__ float g_c[HID];               // edge_emb_b @ W1 + b1
__device__ float g_cvec[HID];            // mean_bio @ head_W1[HID:] + head_b1
// CSR-by-dst
__device__ int g_deg[N_NODES];
__device__ int g_cur[N_NODES];
__device__ int g_rowptr[N_NODES];
__device__ int g_perm[N_EDGES];

// ---------------- small helpers ----------------
__global__ void k_zero_cnt() {
    int i = threadIdx.x;
    if (i < N_GRAPHS) g_cnt[i] = 0.f;
}

__global__ void k_count(const int* __restrict__ batch) {
    int i = blockIdx.x * 256 + threadIdx.x;
    if (i < N_NODES) atomicAdd(&g_cnt[batch[i]], 1.0f);
}

__global__ void k_zero_stats() {
    int i = blockIdx.x * 256 + threadIdx.x;
    if (i < N_GRAPHS * HID) { g_gsum[i] = 0.f; g_gsq[i] = 0.f; }
}

// Precompute M4 = We@W1 (4x256), c = be@W1 + b1, cvec = bio@W1b + hb1
__global__ void k_prep(const float* __restrict__ We, const float* __restrict__ be,
                       const float* __restrict__ W1, const float* __restrict__ b1,
                       const float* __restrict__ bio, const float* __restrict__ hW1,
                       const float* __restrict__ hb1) {
    int k = threadIdx.x;  // 0..255
    if (blockIdx.x == 0) {
        float c = b1[k];
        #pragma unroll 4
        for (int i = 0; i < HID; i++) c += be[i] * W1[i * HID + k];
        g_c[k] = c;
        #pragma unroll
        for (int j = 0; j < 4; j++) {
            float m = 0.f;
            #pragma unroll 4
            for (int i = 0; i < HID; i++) m += We[j * HID + i] * W1[i * HID + k];
            g_M4[j * HID + k] = m;
        }
    } else {
        float cv = hb1[k];
        #pragma unroll 4
        for (int i = 0; i < 512; i++) cv += bio[i] * hW1[(HID + i) * HID + k];
        g_cvec[k] = cv;
    }
}

__global__ void k_embed(const int* __restrict__ x, const float* __restrict__ embW) {
    int idx = blockIdx.x * 256 + threadIdx.x;
    if (idx >= N_NODES * 64) return;
    int node = idx >> 6, ch = idx & 63;
    ((float4*)g_h)[node * 64 + ch] = ((const float4*)embW)[x[node] * 64 + ch];
}

// ---------------- CSR-by-dst construction ----------------
__global__ void k_zero_misc() {
    int i = blockIdx.x * 256 + threadIdx.x;
    if (i < N_NODES) { g_deg[i] = 0; g_cur[i] = 0; }
}

__global__ void k_hist(const int* __restrict__ dst) {
    int e = blockIdx.x * 256 + threadIdx.x;
    if (e < N_EDGES) atomicAdd(&g_deg[dst[e]], 1);
}

// single-block exclusive scan of g_deg -> g_rowptr
__global__ void k_scan() {
    __shared__ int s[1024];
    __shared__ int off;
    int tid = threadIdx.x;
    if (tid == 0) off = 0;
    __syncthreads();
    for (int base = 0; base < N_NODES; base += 1024) {
        int v = (base + tid < N_NODES) ? g_deg[base + tid] : 0;
        s[tid] = v;
        __syncthreads();
        for (int d = 1; d < 1024; d <<= 1) {
            int t = (tid >= d) ? s[tid - d] : 0;
            __syncthreads();
            s[tid] += t;
            __syncthreads();
        }
        if (base + tid < N_NODES) g_rowptr[base + tid] = s[tid] - v + off;
        __syncthreads();
        if (tid == 0) off += s[1023];
        __syncthreads();
    }
}

__global__ void k_fill(const int* __restrict__ dst) {
    int e = blockIdx.x * 256 + threadIdx.x;
    if (e >= N_EDGES) return;
    int d = dst[e];
    int pos = g_rowptr[d] + atomicAdd(&g_cur[d], 1);
    g_perm[pos] = e;
}

// ---------------- aggregation: z[n] = (1+eps)*h[n] + sum_{e in CSR[n]} relu(h[src]+e)
__global__ void k_agg(const int* __restrict__ src, const float* __restrict__ epsp) {
    __shared__ float s_eps;
    int n = blockIdx.x;
    int c = threadIdx.x;
    if (c == 0) s_eps = 1.0f + *epsp;
    __syncthreads();
    int start = g_rowptr[n];
    int deg = g_deg[n];
    float acc = s_eps * g_h[(size_t)n * HID + c];
    for (int i = 0; i < deg; i++) {
        int e = __ldg(&g_perm[start + i]);
        int s = __ldg(&src[e]);
        acc += fmaxf(g_h[(size_t)s * HID + c] + g_e[(size_t)e * HID + c], 0.f);
    }
    g_z[(size_t)n * HID + c] = acc;
}

// ---------------- GEMM: C[M,256] = epilogue(A[M,256] @ B[256,256] + bias) ---------------
// MODE 0: A direct, no activation     (t @ W2 + b2 -> h)
// MODE 1: A direct, relu output       (z @ W1 + b1 -> t)
// MODE 2: A implicit = relu(edge_attr@M4 + c); output scaled by struct mask
template <int MODE>
__global__ void __launch_bounds__(256) k_gemm(
    const float* __restrict__ A, const float* __restrict__ B,
    const float* __restrict__ bias, float* __restrict__ C, int M,
    const float* __restrict__ ssp) {
    __shared__ float As[2][KSTEP][128];
    __shared__ float Bs[2][KSTEP][128];
    __shared__ float4 ea_s[128];
    __shared__ float M4s[4][HID];
    __shared__ float cs[HID];

    const int tid = threadIdx.x;
    const int bm = blockIdx.x * 128;
    const int bn = blockIdx.y * 128;
    const int tx = tid & 15;
    const int ty = tid >> 4;

    const int fm = tid & 127;
    const int fk0 = tid >> 7;
    float4 eav = make_float4(0.f, 0.f, 0.f, 0.f);

    if (MODE == 2) {
        if (tid < 128) {
            int r = bm + tid;
            ea_s[tid] = (r < M) ? ((const float4*)A)[r] : make_float4(0.f, 0.f, 0.f, 0.f);
        }
        ((float4*)M4s)[tid] = ((const float4*)g_M4)[tid];
        cs[tid] = g_c[tid];
        __syncthreads();
        eav = ea_s[fm];
    }

    float4 ra[2], rb[2];
    const int a_m = tid & 127;
    const int a_kg = tid >> 7;
    const int b_k = tid >> 5;
    const int b_n4 = tid & 31;

    if (MODE == 2) {
        #pragma unroll
        for (int l = 0; l < 8; l++) {
            int k = fk0 + l * 2;
            float v = cs[k] + eav.x * M4s[0][k] + eav.y * M4s[1][k]
                    + eav.z * M4s[2][k] + eav.w * M4s[3][k];
            As[0][k][fm] = fmaxf(v, 0.f);
        }
    } else {
        #pragma unroll
        for (int l = 0; l < 2; l++) {
            int kg = a_kg + l * 2;
            int r = bm + a_m;
            ra[l] = (r < M) ? *(const float4*)(A + (size_t)r * HID + kg * 4)
                            : make_float4(0.f, 0.f, 0.f, 0.f);
            As[0][kg * 4 + 0][a_m] = ra[l].x;
            As[0][kg * 4 + 1][a_m] = ra[l].y;
            As[0][kg * 4 + 2][a_m] = ra[l].z;
            As[0][kg * 4 + 3][a_m] = ra[l].w;
        }
    }
    #pragma unroll
    for (int l = 0; l < 2; l++) {
        int k = b_k + l * 8;
        rb[l] = *(const float4*)(B + (size_t)k * HID + bn + b_n4 * 4);
        *(float4*)&Bs[0][k][b_n4 * 4] = rb[l];
    }
    __syncthreads();

    unsigned long long acc[8][4];
    #pragma unroll
    for (int i = 0; i < 8; i++)
        #pragma unroll
        for (int j = 0; j < 4; j++) acc[i][j] = 0ULL;

    for (int t = 0; t < NTILES; t++) {
        const int cur = t & 1, nxt = cur ^ 1;
        const int kc_next = (t + 1) * KSTEP;

        if (t + 1 < NTILES) {
            if (MODE != 2) {
                #pragma unroll
                for (int l = 0; l < 2; l++) {
                    int kg = a_kg + l * 2;
                    int r = bm + a_m;
                    ra[l] = (r < M) ? *(const float4*)(A + (size_t)r * HID + kc_next + kg * 4)
                                    : make_float4(0.f, 0.f, 0.f, 0.f);
                }
            }
            #pragma unroll
            for (int l = 0; l < 2; l++) {
                int k = b_k + l * 8;
                rb[l] = *(const float4*)(B + (size_t)(kc_next + k) * HID + bn + b_n4 * 4);
            }
        }

        #pragma unroll
        for (int k = 0; k < KSTEP; k++) {
            float a[8];
            *(float4*)&a[0] = *(const float4*)&As[cur][k][ty * 8];
            *(float4*)&a[4] = *(const float4*)&As[cur][k][ty * 8 + 4];
            ulonglong2 bq0 = *(const ulonglong2*)&Bs[cur][k][tx * 8];
            ulonglong2 bq1 = *(const ulonglong2*)&Bs[cur][k][tx * 8 + 4];
            unsigned long long b2[4] = {bq0.x, bq0.y, bq1.x, bq1.y};
            #pragma unroll
            for (int i = 0; i < 8; i++) {
                unsigned ai = __float_as_uint(a[i]);
                unsigned long long a2;
                asm("mov.b64 %0, {%1, %1};" : "=l"(a2) : "r"(ai));
                #pragma unroll
                for (int j = 0; j < 4; j++)
                    asm("fma.rn.f32x2 %0, %1, %2, %0;" : "+l"(acc[i][j]) : "l"(a2), "l"(b2[j]));
            }
        }

        if (t + 1 < NTILES) {
            if (MODE == 2) {
                #pragma unroll
                for (int l = 0; l < 8; l++) {
                    int k = fk0 + l * 2;
                    int kk = kc_next + k;
                    float v = cs[kk] + eav.x * M4s[0][kk] + eav.y * M4s[1][kk]
                            + eav.z * M4s[2][kk] + eav.w * M4s[3][kk];
                    As[nxt][k][fm] = fmaxf(v, 0.f);
                }
            } else {
                #pragma unroll
                for (int l = 0; l < 2; l++) {
                    int kg = a_kg + l * 2;
                    As[nxt][kg * 4 + 0][a_m] = ra[l].x;
                    As[nxt][kg * 4 + 1][a_m] = ra[l].y;
                    As[nxt][kg * 4 + 2][a_m] = ra[l].z;
                    As[nxt][kg * 4 + 3][a_m] = ra[l].w;
                }
            }
            #pragma unroll
            for (int l = 0; l < 2; l++) {
                int k = b_k + l * 8;
                *(float4*)&Bs[nxt][k][b_n4 * 4] = rb[l];
            }
        }
        __syncthreads();
    }

    float sscale = 1.f;
    if (MODE == 2) sscale = *ssp;
    float bvals[8];
    *(float4*)&bvals[0] = *(const float4*)(bias + bn + tx * 8);
    *(float4*)&bvals[4] = *(const float4*)(bias + bn + tx * 8 + 4);

    #pragma unroll
    for (int i = 0; i < 8; i++) {
        int r = bm + ty * 8 + i;
        if (r < M) {
            float f = 1.f;
            if (MODE == 2) f = (ea_s[ty * 8 + i].y > 0.f) ? sscale : 1.f;
            float outv[8];
            #pragma unroll
            for (int j = 0; j < 4; j++) {
                float2 p = *(float2*)&acc[i][j];
                outv[2 * j] = p.x;
                outv[2 * j + 1] = p.y;
            }
            #pragma unroll
            for (int jj = 0; jj < 8; jj++) {
                float v = outv[jj] + bvals[jj];
                if (MODE == 1) v = fmaxf(v, 0.f);
                if (MODE == 2) v *= f;
                outv[jj] = v;
            }
            *(float4*)(C + (size_t)r * HID + bn + tx * 8) = *(float4*)&outv[0];
            *(float4*)(C + (size_t)r * HID + bn + tx * 8 + 4) = *(float4*)&outv[4];
        }
    }
}

// ---------------- fused per-graph stats: one pass, Σh and Σh² ----------------
#define STRIP 64

__global__ void k_stats(const float* __restrict__ h, const int* __restrict__ batch) {
    __shared__ int bs[STRIP];
    int c = threadIdx.x;
    int n0 = blockIdx.x * STRIP;
    int n1 = min(n0 + STRIP, N_NODES);
    if (c < STRIP && n0 + c < N_NODES) bs[c] = batch[n0 + c];
    __syncthreads();
    float as = 0.f, aq = 0.f;
    int cur = bs[0];
    for (int n = n0; n < n1; n++) {
        int b = bs[n - n0];
        if (b != cur) {
            atomicAdd(&g_gsum[cur * HID + c], as);
            atomicAdd(&g_gsq[cur * HID + c], aq);
            as = 0.f; aq = 0.f;
            cur = b;
        }
        float v = h[(size_t)n * HID + c];
        as += v;
        aq += v * v;
    }
    atomicAdd(&g_gsum[cur * HID + c], as);
    atomicAdd(&g_gsq[cur * HID + c], aq);
}

// var = E[h^2] - (2a - a^2) * mean^2   (hc = h - a*mean)
__global__ void k_norm2(const int* __restrict__ batch, const float* __restrict__ gamma,
                        const float* __restrict__ beta, const float* __restrict__ alpha) {
    int idx = blockIdx.x * 256 + threadIdx.x;
    if (idx >= N_NODES * HID) return;
    int node = idx >> 8, c = idx & 255;
    int b = batch[node];
    float a = alpha[c];
    float inv = 1.f / fmaxf(g_cnt[b], 1.f);
    float mean = g_gsum[b * HID + c] * inv;
    float msq = g_gsq[b * HID + c] * inv;
    float var = msq - (2.f * a - a * a) * mean * mean;
    float hc = g_h[idx] - a * mean;
    g_h[idx] = gamma[c] * hc * rsqrtf(var + EPSN) + beta[c];
}

// ---------------- head ----------------
__global__ void k_head(const float* __restrict__ headW1, const float* __restrict__ headW2,
                       const float* __restrict__ headb2, float* __restrict__ out) {
    int g = blockIdx.x;
    int j = threadIdx.x;
    __shared__ float gs[HID];
    __shared__ float red[HID];
    float inv = 1.f / fmaxf(g_cnt[g], 1.f);
    gs[j] = g_gsum[g * HID + j] * inv;
    __syncthreads();
    float acc = g_cvec[j];
    #pragma unroll 8
    for (int k = 0; k < HID; k++) acc += gs[k] * headW1[k * HID + j];
    acc = fmaxf(acc, 0.f);
    red[j] = acc * headW2[j];
    __syncthreads();
    for (int s = 128; s > 0; s >>= 1) {
        if (j < s) red[j] += red[j + s];
        __syncthreads();
    }
    if (j == 0) out[g] = red[0] + headb2[0];
}

// ---------------- launcher ----------------
extern "C" void kernel_launch(void* const* d_in, const int* in_sizes, int n_in,
                              void* d_out, int out_size) {
    const int* x = (const int*)d_in[0];
    const int* edge_index = (const int*)d_in[1];
    const float* edge_attr = (const float*)d_in[2];
    const int* batch = (const int*)d_in[3];
    const float* node_emb_W = (const float*)d_in[4];
    const float* edge_emb_W = (const float*)d_in[5];
    const float* edge_emb_b = (const float*)d_in[6];
    const float* edge_mlp_W1 = (const float*)d_in[7];
    const float* edge_mlp_b1 = (const float*)d_in[8];
    const float* edge_mlp_W2 = (const float*)d_in[9];
    const float* edge_mlp_b2 = (const float*)d_in[10];
    const float* struct_scale = (const float*)d_in[11];
    const float* conv_W1 = (const float*)d_in[12];
    const float* conv_b1 = (const float*)d_in[13];
    const float* conv_W2 = (const float*)d_in[14];
    const float* conv_b2 = (const float*)d_in[15];
    const float* conv_eps = (const float*)d_in[16];
    const float* norm_gamma = (const float*)d_in[17];
    const float* norm_beta = (const float*)d_in[18];
    const float* norm_alpha = (const float*)d_in[19];
    const float* head_W1 = (const float*)d_in[21];
    const float* head_W2 = (const float*)d_in[23];
    const float* head_b2 = (const float*)d_in[24];
    float* out = (float*)d_out;

    const int* src = edge_index;
    const int* dst = edge_index + N_EDGES;

    // launches 1-3
    k_zero_cnt<<<1, 256>>>();
    k_count<<<(N_NODES + 255) / 256, 256>>>(batch);
    k_prep<<<2, 256>>>(edge_emb_W, edge_emb_b, edge_mlp_W1, edge_mlp_b1,
                       (const float*)d_in[20], head_W1, (const float*)d_in[22]);

    // launch 4 (profiled slot): big edge GEMM
    k_gemm<2><<<dim3(N_EDGES / 128, 2), 256>>>(edge_attr, edge_mlp_W2, edge_mlp_b2,
                                               g_e, N_EDGES, struct_scale);

    k_embed<<<(N_NODES * 64 + 255) / 256, 256>>>(x, node_emb_W);

    // CSR-by-dst build (reused every layer)
    k_zero_misc<<<(N_NODES + 255) / 256, 256>>>();
    k_hist<<<(N_EDGES + 255) / 256, 256>>>(dst);
    k_scan<<<1, 1024>>>();
    k_fill<<<(N_EDGES + 255) / 256, 256>>>(dst);

    const int gemm_mx = (N_NODES + 127) / 128;
    for (int l = 0; l < LAYERS; l++) {
        k_agg<<<N_NODES, 256>>>(src, conv_eps + l);
        k_gemm<1><<<dim3(gemm_mx, 2), 256>>>(g_z, conv_W1 + (size_t)l * HID * HID,
                                             conv_b1 + l * HID, g_t, N_NODES, nullptr);
        k_gemm<0><<<dim3(gemm_mx, 2), 256>>>(g_t, conv_W2 + (size_t)l * HID * HID,
                                             conv_b2 + l * HID, g_h, N_NODES, nullptr);
        k_zero_stats<<<(N_GRAPHS * HID + 255) / 256, 256>>>();
        k_stats<<<(N_NODES + STRIP - 1) / STRIP, 256>>>(g_h, batch);
        k_norm2<<<(N_NODES * HID + 255) / 256, 256>>>(batch, norm_gamma + l * HID,
                                                      norm_beta + l * HID, norm_alpha + l * HID);
    }

    // pool + head
    k_zero_stats<<<(N_GRAPHS * HID + 255) / 256, 256>>>();
    k_stats<<<(N_NODES + STRIP - 1) / STRIP, 256>>>(g_h, batch);
    k_head<<<N_GRAPHS, 256>>>(head_W1, head_W2, head_b2, out);
}